// round 8
// baseline (speedup 1.0000x reference)
#include <cuda_runtime.h>
#include <cuda_bf16.h>
#include <cuda_fp16.h>
#include <cstdint>

// BatchSRU: L=2048, B=8, D=128, NB=16, fp32. HMMA mma.sync bf16, 3-combo fp32
// emulation. Pass1: transpose+split x -> g_xhi/g_xlo [b][nb][t][k].
// Pass2: TWO CTAs per (b,nb) (channel halves of 64), 2 CTAs/SM resident:
//        W^T(192 rows) hi/lo in SMEM, all 8 warps GEMM per 16-step tile,
//        scan (threads 0-63) writes h coalesced to g_hT; x for highway read
//        straight from g_xhi/g_xlo (global, coalesced).
// Pass3: untranspose g_hT -> out(l,b,d,nb).

#define L_SEQ 2048
#define BATCH 8
#define DIM   128
#define NBI   16
#define NT    16
#define NTILES 128

__device__ __nv_bfloat16 g_xhi[BATCH * NBI * L_SEQ * DIM];
__device__ __nv_bfloat16 g_xlo[BATCH * NBI * L_SEQ * DIM];
__device__ float         g_hT [BATCH * NBI * L_SEQ * DIM];

// SMEM byte offsets (per-CTA total 114688 B -> 2 CTAs/SM)
#define OFF_WHI 0            // 192 rows x 256 B
#define OFF_WLO 49152        // 192 rows x 256 B
#define OFF_XB  98304        // x tile: hi 4096 + lo 4096 (single buffer)
#define OFF_UX  106496       // fp32 [16][64]
#define OFF_UF  110592       // fp16 [16][64]
#define OFF_UR  112640       // fp16 [16][64]
#define SMEM_MAIN 114688

__device__ __forceinline__ uint32_t smem_u32(const void* p) {
    uint32_t a;
    asm("{ .reg .u64 t; cvta.to.shared.u64 t, %1; cvt.u32.u64 %0, t; }" : "=r"(a) : "l"(p));
    return a;
}
__device__ __forceinline__ void ldsm_x4(uint32_t* r, uint32_t addr) {
    asm volatile("ldmatrix.sync.aligned.m8n8.x4.shared.b16 {%0,%1,%2,%3}, [%4];"
                 : "=r"(r[0]), "=r"(r[1]), "=r"(r[2]), "=r"(r[3]) : "r"(addr));
}
__device__ __forceinline__ void ldsm_x2(uint32_t* r, uint32_t addr) {
    asm volatile("ldmatrix.sync.aligned.m8n8.x2.shared.b16 {%0,%1}, [%2];"
                 : "=r"(r[0]), "=r"(r[1]) : "r"(addr));
}
__device__ __forceinline__ void mma_bf16(float* d, const uint32_t* a, const uint32_t* b) {
    asm volatile("mma.sync.aligned.m16n8k16.row.col.f32.bf16.bf16.f32 "
                 "{%0,%1,%2,%3}, {%4,%5,%6,%7}, {%8,%9}, {%0,%1,%2,%3};"
                 : "+f"(d[0]), "+f"(d[1]), "+f"(d[2]), "+f"(d[3])
                 : "r"(a[0]), "r"(a[1]), "r"(a[2]), "r"(a[3]), "r"(b[0]), "r"(b[1]));
}
__device__ __forceinline__ float sigf(float z) {
    return __fdividef(1.0f, 1.0f + __expf(-z));
}

// ============ Pass 1: transpose + hi/lo split ============
#define TP_T 4
__global__ void __launch_bounds__(256) transpose_x(const float* __restrict__ x) {
    __shared__ float sm[TP_T * 16 * 129];
    const int bx = blockIdx.x;
    const int t0 = (bx >> 3) * TP_T;
    const int b  = bx & 7;
    #pragma unroll 4
    for (int i = 0; i < 32; i++) {
        int idx  = i * 256 + threadIdx.x;
        int tloc = idx >> 11;
        int rem  = idx & 2047;                  // k*16 + nb
        float v = x[((size_t)(t0 + tloc) * BATCH + b) * 2048 + rem];
        sm[(tloc * 16 + (rem & 15)) * 129 + (rem >> 4)] = v;
    }
    __syncthreads();
    #pragma unroll 4
    for (int i = 0; i < 32; i++) {
        int idx = i * 256 + threadIdx.x;
        int k = idx & 127;
        int chunk = idx >> 7;                   // nb*4 + tloc
        int nb = chunk >> 2, tloc = chunk & 3;
        float v = sm[(tloc * 16 + nb) * 129 + k];
        __nv_bfloat16 hi = __float2bfloat16(v);
        __nv_bfloat16 lo = __float2bfloat16(v - __bfloat162float(hi));
        size_t o = ((size_t)(b * NBI + nb) * L_SEQ + t0 + tloc) * DIM + k;
        g_xhi[o] = hi;
        g_xlo[o] = lo;
    }
}

// ============ Pass 3: untranspose h ============
__global__ void __launch_bounds__(256) untranspose_h(float* __restrict__ out) {
    __shared__ float sm[TP_T * 16 * 129];
    const int bx = blockIdx.x;
    const int t0 = (bx >> 3) * TP_T;
    const int b  = bx & 7;
    #pragma unroll 4
    for (int i = 0; i < 32; i++) {
        int idx = i * 256 + threadIdx.x;
        int k = idx & 127;
        int chunk = idx >> 7;
        int nb = chunk >> 2, tloc = chunk & 3;
        sm[(tloc * 16 + nb) * 129 + k] =
            g_hT[((size_t)(b * NBI + nb) * L_SEQ + t0 + tloc) * DIM + k];
    }
    __syncthreads();
    #pragma unroll 4
    for (int i = 0; i < 32; i++) {
        int idx  = i * 256 + threadIdx.x;
        int tloc = idx >> 11;
        int rem  = idx & 2047;
        out[((size_t)(t0 + tloc) * BATCH + b) * 2048 + rem] =
            sm[(tloc * 16 + (rem & 15)) * 129 + (rem >> 4)];
    }
}

// ============ Pass 2: main (2 CTAs per (b,nb); 64 channels each) ============
__global__ void __launch_bounds__(256, 2) sru_main(
    const float* __restrict__ W, const float* __restrict__ bias)
{
    extern __shared__ char sm[];
    const uint32_t sb = smem_u32(sm);
    const int tid  = threadIdx.x;
    const int lane = tid & 31;
    const int w    = tid >> 5;
    const int bx  = blockIdx.x;
    const int bxp = bx >> 1;            // (b*16 + nb)
    const int hh  = bx & 1;             // channel half
    const int nb  = bxp & 15;

    // ---- one-time: W^T (our 192 rows: 3 gates x 64 channels) hi/lo into SMEM
    {
        const float* Wp = W + (size_t)nb * (DIM * 3 * DIM);
        #pragma unroll 4
        for (int it = 0; it < 96; it++) {
            int idx = it * 256 + tid;            // = k*192 + cc
            int k  = idx / 192;
            int cc = idx - k * 192;              // SMEM row: g*64 + hl
            int grow = (cc >> 6) * 128 + hh * 64 + (cc & 63);
            float v = Wp[k * 384 + grow];
            __nv_bfloat16 hi = __float2bfloat16(v);
            __nv_bfloat16 lo = __float2bfloat16(v - __bfloat162float(hi));
            uint32_t byt = (uint32_t)cc * 256 + (((k >> 3) ^ (cc & 15)) << 4) + ((k & 7) * 2);
            *(__nv_bfloat16*)(sm + OFF_WHI + byt) = hi;
            *(__nv_bfloat16*)(sm + OFF_WLO + byt) = lo;
        }
    }
    // ---- stage XB(0) (threads 64..191)
    if (tid >= 64 && tid < 192) {
        int s = tid - 64, t = s >> 3, cc = (s & 7) * 2;
        size_t o = ((size_t)bxp * L_SEQ + t) * DIM + (s & 7) * 16;
        const uint4* ph = (const uint4*)(g_xhi + o);
        const uint4* pl = (const uint4*)(g_xlo + o);
        uint4 H0 = ph[0], H1 = ph[1], L0 = pl[0], L1 = pl[1];
        uint32_t base = OFF_XB + (uint32_t)t * 256;
        *(uint4*)(sm + base + ((cc ^ t) << 4))       = H0;
        *(uint4*)(sm + base + (((cc + 1) ^ t) << 4)) = H1;
        *(uint4*)(sm + base + 4096 + ((cc ^ t) << 4))       = L0;
        *(uint4*)(sm + base + 4096 + (((cc + 1) ^ t) << 4)) = L1;
    }
    // ---- scan-thread init (threads 0..63; channel jg = hh*64 + tid)
    const int jl = tid;
    const int jg = hh * 64 + jl;
    float bfv = 0.0f, brv = 0.0f;
    if (tid < 64) {
        bfv = bias[nb * 256 + jg];
        brv = bias[nb * 256 + 128 + jg];
    }
    float c = 0.0f;

    // GEMM lane/warp constants
    const int a_tile    = lane >> 3;
    const int a_row_add = (lane & 7) + ((a_tile & 1) << 3);
    const int a_chalf   = a_tile >> 1;
    const int b_row     = lane & 7;
    const int b_chalf   = (lane >> 3) & 1;
    const int g_l  = lane >> 2;
    const int tg   = lane & 3;
    const int m0   = w >> 1;            // local mtile row-block (0..3)
    const int ntw  = w & 1;             // n-tile (t-half) this warp owns
    __syncthreads();

    for (int i = 0; i < NTILES; i++) {
        // -- prefetch x(i+1) into regs (threads 64..191), overlaps GEMM
        uint4 H0, H1, L0, L1;
        if (tid >= 64 && tid < 192 && i + 1 < NTILES) {
            int s = tid - 64;
            size_t o = ((size_t)bxp * L_SEQ + (size_t)(i + 1) * NT + (s >> 3)) * DIM + (s & 7) * 16;
            const uint4* ph = (const uint4*)(g_xhi + o);
            const uint4* pl = (const uint4*)(g_xlo + o);
            H0 = ph[0]; H1 = ph[1]; L0 = pl[0]; L1 = pl[1];
        }

        // ---------- phase A: GEMM (all 8 warps; warp = (m0, ntw), 3 gates)
        float D[3][4];
        #pragma unroll
        for (int gg = 0; gg < 3; gg++)
            #pragma unroll
            for (int e = 0; e < 4; e++) D[gg][e] = 0.0f;

        #pragma unroll
        for (int ks = 0; ks < 8; ks++) {
            uint32_t Bhi[2], Blo[2];
            {
                int trow = ntw * 8 + b_row;
                uint32_t ba = sb + OFF_XB + trow * 256 + (((2 * ks + b_chalf) ^ trow) << 4);
                ldsm_x2(Bhi, ba);
                ldsm_x2(Blo, ba + 4096);
            }
            #pragma unroll
            for (int gg = 0; gg < 3; gg++) {
                int row = (gg * 4 + m0) * 16 + a_row_add;
                uint32_t aa = sb + OFF_WHI + row * 256 +
                              (((2 * ks + a_chalf) ^ (row & 15)) << 4);
                uint32_t Ahi[4], Alo[4];
                ldsm_x4(Ahi, aa);
                ldsm_x4(Alo, aa + (OFF_WLO - OFF_WHI));
                mma_bf16(D[gg], Ahi, Bhi);
                mma_bf16(D[gg], Alo, Bhi);
                mma_bf16(D[gg], Ahi, Blo);
            }
        }
        // -- store U (gate0 fp32, gates f/r fp16), rows 64-wide
        {
            int h0 = m0 * 16 + g_l;
            int t0 = ntw * 8 + tg * 2;
            float* ux = (float*)(sm + OFF_UX);
            ux[(t0)     * 64 + h0]     = D[0][0];
            ux[(t0 + 1) * 64 + h0]     = D[0][1];
            ux[(t0)     * 64 + h0 + 8] = D[0][2];
            ux[(t0 + 1) * 64 + h0 + 8] = D[0][3];
            __half* uf = (__half*)(sm + OFF_UF);
            uf[(t0)     * 64 + h0]     = __float2half_rn(D[1][0]);
            uf[(t0 + 1) * 64 + h0]     = __float2half_rn(D[1][1]);
            uf[(t0)     * 64 + h0 + 8] = __float2half_rn(D[1][2]);
            uf[(t0 + 1) * 64 + h0 + 8] = __float2half_rn(D[1][3]);
            __half* ur = (__half*)(sm + OFF_UR);
            ur[(t0)     * 64 + h0]     = __float2half_rn(D[2][0]);
            ur[(t0 + 1) * 64 + h0]     = __float2half_rn(D[2][1]);
            ur[(t0)     * 64 + h0 + 8] = __float2half_rn(D[2][2]);
            ur[(t0 + 1) * 64 + h0 + 8] = __float2half_rn(D[2][3]);
        }
        __syncthreads();                        // U ready; XB reads done

        // ---------- phase B: scan (threads 0..63) | stage XB(i+1) (64..191)
        if (tid < 64) {
            const float*  ux = (const float*)(sm + OFF_UX);
            const __half* uf = (const __half*)(sm + OFF_UF);
            const __half* ur = (const __half*)(sm + OFF_UR);
            // highway x from global (coalesced; issue all loads up front)
            const __nv_bfloat16* xh = g_xhi + ((size_t)bxp * L_SEQ + (size_t)i * NT) * DIM + jg;
            const __nv_bfloat16* xl = g_xlo + ((size_t)bxp * L_SEQ + (size_t)i * NT) * DIM + jg;
            float xv[NT];
            #pragma unroll
            for (int t = 0; t < NT; t++)
                xv[t] = __bfloat162float(xh[t * DIM]) + __bfloat162float(xl[t * DIM]);
            float* hp = g_hT + ((size_t)bxp * L_SEQ + (size_t)i * NT) * DIM + jg;
            #pragma unroll
            for (int t = 0; t < NT; t++) {
                float xt = ux[t * 64 + jl];
                float fv = sigf(__half2float(uf[t * 64 + jl]) + bfv);
                float rv = sigf(__half2float(ur[t * 64 + jl]) + brv);
                c = fmaf(fv, c - xt, xt);
                hp[t * DIM] = fmaf(rv, c - xv[t], xv[t]);
            }
        } else if (tid < 192 && i + 1 < NTILES) {
            int s = tid - 64, t = s >> 3, cc = (s & 7) * 2;
            uint32_t base = OFF_XB + (uint32_t)t * 256;
            *(uint4*)(sm + base + ((cc ^ t) << 4))       = H0;
            *(uint4*)(sm + base + (((cc + 1) ^ t) << 4)) = H1;
            *(uint4*)(sm + base + 4096 + ((cc ^ t) << 4))       = L0;
            *(uint4*)(sm + base + 4096 + (((cc + 1) ^ t) << 4)) = L1;
        }
        __syncthreads();                        // XB(i+1) staged; U free
    }
}

extern "C" void kernel_launch(void* const* d_in, const int* in_sizes, int n_in,
                              void* d_out, int out_size) {
    const float* x  = (const float*)d_in[0];
    const float* W  = (const float*)d_in[1];
    const float* bi = (const float*)d_in[2];
    float* out = (float*)d_out;

    transpose_x<<<(L_SEQ / TP_T) * BATCH, 256>>>(x);
    cudaFuncSetAttribute(sru_main, cudaFuncAttributeMaxDynamicSharedMemorySize, SMEM_MAIN);
    sru_main<<<BATCH * NBI * 2, 256, SMEM_MAIN>>>(W, bi);
    untranspose_h<<<(L_SEQ / TP_T) * BATCH, 256>>>(out);
}

// round 9
// speedup vs baseline: 1.1801x; 1.1801x over previous
#include <cuda_runtime.h>
#include <cuda_bf16.h>
#include <cuda_fp16.h>
#include <cstdint>

// BatchSRU: L=2048, B=8, D=128, NB=16, fp32. HMMA mma.sync bf16, 3-combo fp32
// emulation. Pass1: transpose+split x -> g_xhi/g_xlo [b][nb][t][k].
// Pass2: per-(b,nb) CTA. W^T fragments loaded ONCE into registers
//        (Ah/Al[3][8][4] per thread), W SMEM freed and overlaid with XB/U.
//        Per 16-step tile: all 8 warps GEMM (4 ldsm_x2 + 18 mma per ks),
//        scan (warps 0-3) writes h coalesced to g_hT.
// Pass3: untranspose g_hT -> out(l,b,d,nb).

#define L_SEQ 2048
#define BATCH 8
#define DIM   128
#define NBI   16
#define NT    16
#define NTILES 128

__device__ __nv_bfloat16 g_xhi[BATCH * NBI * L_SEQ * DIM];
__device__ __nv_bfloat16 g_xlo[BATCH * NBI * L_SEQ * DIM];
__device__ float         g_hT [BATCH * NBI * L_SEQ * DIM];

// ---- SMEM: W staging (startup only) overlays the steady-state buffers
#define OFF_WHI 0            // startup: 384 rows x 256 B
#define OFF_WLO 98304        // startup: 384 rows x 256 B
#define OFF_XB  0            // steady: 2 bufs x (hi 4096 + lo 4096)
#define OFF_UX  16384        // fp32 [16][128]
#define OFF_UF  24576        // fp16 [16][128]
#define OFF_UR  28672        // fp16 [16][128]
#define SMEM_MAIN 196608

__device__ __forceinline__ uint32_t smem_u32(const void* p) {
    uint32_t a;
    asm("{ .reg .u64 t; cvta.to.shared.u64 t, %1; cvt.u32.u64 %0, t; }" : "=r"(a) : "l"(p));
    return a;
}
__device__ __forceinline__ void ldsm_x4(uint32_t* r, uint32_t addr) {
    asm volatile("ldmatrix.sync.aligned.m8n8.x4.shared.b16 {%0,%1,%2,%3}, [%4];"
                 : "=r"(r[0]), "=r"(r[1]), "=r"(r[2]), "=r"(r[3]) : "r"(addr));
}
__device__ __forceinline__ void ldsm_x2(uint32_t* r, uint32_t addr) {
    asm volatile("ldmatrix.sync.aligned.m8n8.x2.shared.b16 {%0,%1}, [%2];"
                 : "=r"(r[0]), "=r"(r[1]) : "r"(addr));
}
__device__ __forceinline__ void mma_bf16(float* d, const uint32_t* a, const uint32_t* b) {
    asm volatile("mma.sync.aligned.m16n8k16.row.col.f32.bf16.bf16.f32 "
                 "{%0,%1,%2,%3}, {%4,%5,%6,%7}, {%8,%9}, {%0,%1,%2,%3};"
                 : "+f"(d[0]), "+f"(d[1]), "+f"(d[2]), "+f"(d[3])
                 : "r"(a[0]), "r"(a[1]), "r"(a[2]), "r"(a[3]), "r"(b[0]), "r"(b[1]));
}
__device__ __forceinline__ float sigf(float z) {
    return __fdividef(1.0f, 1.0f + __expf(-z));
}

// ============ Pass 1: transpose + hi/lo split ============
#define TP_T 4
__global__ void __launch_bounds__(256) transpose_x(const float* __restrict__ x) {
    __shared__ float sm[TP_T * 16 * 129];
    const int bx = blockIdx.x;
    const int t0 = (bx >> 3) * TP_T;
    const int b  = bx & 7;
    #pragma unroll 4
    for (int i = 0; i < 32; i++) {
        int idx  = i * 256 + threadIdx.x;
        int tloc = idx >> 11;
        int rem  = idx & 2047;                  // k*16 + nb
        float v = x[((size_t)(t0 + tloc) * BATCH + b) * 2048 + rem];
        sm[(tloc * 16 + (rem & 15)) * 129 + (rem >> 4)] = v;
    }
    __syncthreads();
    #pragma unroll 4
    for (int i = 0; i < 32; i++) {
        int idx = i * 256 + threadIdx.x;
        int k = idx & 127;
        int chunk = idx >> 7;                   // nb*4 + tloc
        int nb = chunk >> 2, tloc = chunk & 3;
        float v = sm[(tloc * 16 + nb) * 129 + k];
        __nv_bfloat16 hi = __float2bfloat16(v);
        __nv_bfloat16 lo = __float2bfloat16(v - __bfloat162float(hi));
        size_t o = ((size_t)(b * NBI + nb) * L_SEQ + t0 + tloc) * DIM + k;
        g_xhi[o] = hi;
        g_xlo[o] = lo;
    }
}

// ============ Pass 3: untranspose h ============
__global__ void __launch_bounds__(256) untranspose_h(float* __restrict__ out) {
    __shared__ float sm[TP_T * 16 * 129];
    const int bx = blockIdx.x;
    const int t0 = (bx >> 3) * TP_T;
    const int b  = bx & 7;
    #pragma unroll 4
    for (int i = 0; i < 32; i++) {
        int idx = i * 256 + threadIdx.x;
        int k = idx & 127;
        int chunk = idx >> 7;
        int nb = chunk >> 2, tloc = chunk & 3;
        sm[(tloc * 16 + nb) * 129 + k] =
            g_hT[((size_t)(b * NBI + nb) * L_SEQ + t0 + tloc) * DIM + k];
    }
    __syncthreads();
    #pragma unroll 4
    for (int i = 0; i < 32; i++) {
        int idx  = i * 256 + threadIdx.x;
        int tloc = idx >> 11;
        int rem  = idx & 2047;
        out[((size_t)(t0 + tloc) * BATCH + b) * 2048 + rem] =
            sm[(tloc * 16 + (rem & 15)) * 129 + (rem >> 4)];
    }
}

// ============ Pass 2: main ============
__global__ void __launch_bounds__(256, 1) sru_main(
    const float* __restrict__ W, const float* __restrict__ bias)
{
    extern __shared__ char sm[];
    const uint32_t sb = smem_u32(sm);
    const int tid  = threadIdx.x;
    const int lane = tid & 31;
    const int w    = tid >> 5;
    const int bx = blockIdx.x, nb = bx & 15;

    // GEMM lane/warp constants
    const int a_tile    = lane >> 3;
    const int a_row_add = (lane & 7) + ((a_tile & 1) << 3);
    const int a_chalf   = a_tile >> 1;
    const int b_row     = lane & 7;
    const int b_chalf   = (lane >> 3) & 1;
    const int g  = lane >> 2;
    const int tg = lane & 3;

    // ---- startup: stage W^T hi/lo into SMEM, then hoist fragments to regs
    {
        const float* Wp = W + (size_t)nb * (DIM * 3 * DIM);
        #pragma unroll 4
        for (int it = 0; it < 192; it++) {
            int idx = it * 256 + tid;            // = k*384 + h
            int k = idx / 384, h = idx - k * 384;
            float v = Wp[idx];
            __nv_bfloat16 hi = __float2bfloat16(v);
            __nv_bfloat16 lo = __float2bfloat16(v - __bfloat162float(hi));
            uint32_t byt = (uint32_t)h * 256 + (((k >> 3) ^ (h & 15)) << 4) + ((k & 7) * 2);
            *(__nv_bfloat16*)(sm + OFF_WHI + byt) = hi;
            *(__nv_bfloat16*)(sm + OFF_WLO + byt) = lo;
        }
    }
    __syncthreads();

    uint32_t Ah[3][8][4], Al[3][8][4];          // per-thread A fragments (192 regs)
    #pragma unroll
    for (int mi = 0; mi < 3; mi++) {
        int mt  = w * 3 + mi;
        int row = mt * 16 + a_row_add;
        #pragma unroll
        for (int ks = 0; ks < 8; ks++) {
            uint32_t aa = sb + OFF_WHI + row * 256 +
                          (((2 * ks + a_chalf) ^ (row & 15)) << 4);
            ldsm_x4(Ah[mi][ks], aa);
            ldsm_x4(Al[mi][ks], aa + (OFF_WLO - OFF_WHI));
        }
    }
    __syncthreads();                             // W SMEM now dead; overlay buffers

    // ---- stage XB(0) (warps 4-7)
    const int s = tid - 128;
    if (w >= 4) {
        int t = s >> 3, cc = (s & 7) * 2;
        size_t o = ((size_t)bx * L_SEQ + t) * DIM + (s & 7) * 16;
        const uint4* ph = (const uint4*)(g_xhi + o);
        const uint4* pl = (const uint4*)(g_xlo + o);
        uint4 H0 = ph[0], H1 = ph[1], L0 = pl[0], L1 = pl[1];
        uint32_t base = OFF_XB + (uint32_t)t * 256;
        *(uint4*)(sm + base + ((cc ^ t) << 4))       = H0;
        *(uint4*)(sm + base + (((cc + 1) ^ t) << 4)) = H1;
        *(uint4*)(sm + base + 4096 + ((cc ^ t) << 4))       = L0;
        *(uint4*)(sm + base + 4096 + (((cc + 1) ^ t) << 4)) = L1;
    }
    const int j = tid & 127;
    const float bfv = bias[nb * 256 + j];
    const float brv = bias[nb * 256 + 128 + j];
    float c = 0.0f;
    __syncthreads();

    for (int i = 0; i < NTILES; i++) {
        const int buf = i & 1;

        // -- prefetch x(i+1) (warps 4-7): LDG now, STS at end of phase A into
        //    the write-side buffer (read next iteration, after 2 barriers)
        uint4 H0, H1, L0, L1;
        const bool do_stage = (w >= 4) && (i + 1 < NTILES);
        if (do_stage) {
            size_t o = ((size_t)bx * L_SEQ + (size_t)(i + 1) * NT + (s >> 3)) * DIM + (s & 7) * 16;
            const uint4* ph = (const uint4*)(g_xhi + o);
            const uint4* pl = (const uint4*)(g_xlo + o);
            H0 = ph[0]; H1 = ph[1]; L0 = pl[0]; L1 = pl[1];
        }

        // ---------- phase A: GEMM (all 8 warps; A from registers)
        float D[3][2][4];
        #pragma unroll
        for (int mi = 0; mi < 3; mi++)
            #pragma unroll
            for (int nt = 0; nt < 2; nt++)
                #pragma unroll
                for (int e = 0; e < 4; e++) D[mi][nt][e] = 0.0f;

        const uint32_t xb = sb + OFF_XB + (uint32_t)buf * 8192;
        #pragma unroll
        for (int ks = 0; ks < 8; ks++) {
            uint32_t Bhi[2][2], Blo[2][2];
            #pragma unroll
            for (int nt = 0; nt < 2; nt++) {
                int trow = nt * 8 + b_row;
                uint32_t ba = xb + trow * 256 + (((2 * ks + b_chalf) ^ trow) << 4);
                ldsm_x2(Bhi[nt], ba);
                ldsm_x2(Blo[nt], ba + 4096);
            }
            #pragma unroll
            for (int mi = 0; mi < 3; mi++) {
                #pragma unroll
                for (int nt = 0; nt < 2; nt++) {
                    mma_bf16(D[mi][nt], Ah[mi][ks], Bhi[nt]);
                    mma_bf16(D[mi][nt], Al[mi][ks], Bhi[nt]);
                    mma_bf16(D[mi][nt], Ah[mi][ks], Blo[nt]);
                }
            }
        }
        // -- store U
        #pragma unroll
        for (int mi = 0; mi < 3; mi++) {
            int mt = w * 3 + mi;
            int gate = mt >> 3;
            int h0 = (mt & 7) * 16 + g;
            #pragma unroll
            for (int nt = 0; nt < 2; nt++) {
                int t0 = nt * 8 + tg * 2;
                if (gate == 0) {
                    float* u = (float*)(sm + OFF_UX);
                    u[(t0)     * DIM + h0]     = D[mi][nt][0];
                    u[(t0 + 1) * DIM + h0]     = D[mi][nt][1];
                    u[(t0)     * DIM + h0 + 8] = D[mi][nt][2];
                    u[(t0 + 1) * DIM + h0 + 8] = D[mi][nt][3];
                } else {
                    __half* u = (__half*)(sm + (gate == 1 ? OFF_UF : OFF_UR));
                    u[(t0)     * DIM + h0]     = __float2half_rn(D[mi][nt][0]);
                    u[(t0 + 1) * DIM + h0]     = __float2half_rn(D[mi][nt][1]);
                    u[(t0)     * DIM + h0 + 8] = __float2half_rn(D[mi][nt][2]);
                    u[(t0 + 1) * DIM + h0 + 8] = __float2half_rn(D[mi][nt][3]);
                }
            }
        }
        // -- STS x(i+1) into write-side buffer (not read until next phase A)
        if (do_stage) {
            int t = s >> 3, cc = (s & 7) * 2;
            uint32_t base = OFF_XB + (uint32_t)((i + 1) & 1) * 8192 + (uint32_t)t * 256;
            *(uint4*)(sm + base + ((cc ^ t) << 4))       = H0;
            *(uint4*)(sm + base + (((cc + 1) ^ t) << 4)) = H1;
            *(uint4*)(sm + base + 4096 + ((cc ^ t) << 4))       = L0;
            *(uint4*)(sm + base + 4096 + (((cc + 1) ^ t) << 4)) = L1;
        }
        __syncthreads();                         // U ready

        // ---------- phase B: scan (warps 0-3, coalesced h store)
        if (w < 4) {
            const float*  ux = (const float*)(sm + OFF_UX);
            const __half* uf = (const __half*)(sm + OFF_UF);
            const __half* ur = (const __half*)(sm + OFF_UR);
            const uint32_t xbb = OFF_XB + (uint32_t)buf * 8192;
            float* hp = g_hT + ((size_t)bx * L_SEQ + (size_t)i * NT) * DIM + j;
            #pragma unroll
            for (int t = 0; t < NT; t++) {
                float xt = ux[t * DIM + j];
                float fv = sigf(__half2float(uf[t * DIM + j]) + bfv);
                float rv = sigf(__half2float(ur[t * DIM + j]) + brv);
                c = fmaf(fv, c - xt, xt);
                uint32_t xa = xbb + t * 256 + (((j >> 3) ^ t) << 4) + ((j & 7) * 2);
                float xv = __bfloat162float(*(__nv_bfloat16*)(sm + xa)) +
                           __bfloat162float(*(__nv_bfloat16*)(sm + xa + 4096));
                hp[t * DIM] = fmaf(rv, c - xv, xv);
            }
        }
        __syncthreads();                         // U free; XB(buf) free
    }
}

extern "C" void kernel_launch(void* const* d_in, const int* in_sizes, int n_in,
                              void* d_out, int out_size) {
    const float* x  = (const float*)d_in[0];
    const float* W  = (const float*)d_in[1];
    const float* bi = (const float*)d_in[2];
    float* out = (float*)d_out;

    transpose_x<<<(L_SEQ / TP_T) * BATCH, 256>>>(x);
    cudaFuncSetAttribute(sru_main, cudaFuncAttributeMaxDynamicSharedMemorySize, SMEM_MAIN);
    sru_main<<<BATCH * NBI, 256, SMEM_MAIN>>>(W, bi);
    untranspose_h<<<(L_SEQ / TP_T) * BATCH, 256>>>(out);
}

// round 10
// speedup vs baseline: 1.2611x; 1.0686x over previous
#include <cuda_runtime.h>
#include <cuda_bf16.h>
#include <cuda_fp16.h>
#include <cstdint>

// BatchSRU: L=2048, B=8, D=128, NB=16, fp32. HMMA mma.sync bf16, 3-combo fp32
// emulation. Pass1: transpose+split x -> g_xhi/g_xlo [b][nb][t][k].
// Pass2: per-(b,nb) CTA, 384 threads:
//   warps 4-11 (tid 128..383): GEMM U[h][t]=sum_k W[k][h]x[t][k] (R7 inner loop)
//   warps 0-3  (tid 0..127):  scan of tile i-1 (from regs) CONCURRENT with
//        GEMM(i); phase B drains U(i)+xv(i) to regs and stages XB(i+1).
// Pass3: untranspose g_hT -> out(l,b,d,nb).

#define L_SEQ 2048
#define BATCH 8
#define DIM   128
#define NBI   16
#define NT    16
#define NTILES 128

__device__ __nv_bfloat16 g_xhi[BATCH * NBI * L_SEQ * DIM];
__device__ __nv_bfloat16 g_xlo[BATCH * NBI * L_SEQ * DIM];
__device__ float         g_hT [BATCH * NBI * L_SEQ * DIM];

#define OFF_WHI 0            // 384 rows x 256 B (resident)
#define OFF_WLO 98304
#define OFF_XB  196608       // 2 bufs x (hi 4096 + lo 4096)
#define OFF_UX  212992       // fp32 [16][128]
#define OFF_UF  221184       // fp16 [16][128]
#define OFF_UR  225280       // fp16 [16][128]
#define SMEM_MAIN 229376

__device__ __forceinline__ uint32_t smem_u32(const void* p) {
    uint32_t a;
    asm("{ .reg .u64 t; cvta.to.shared.u64 t, %1; cvt.u32.u64 %0, t; }" : "=r"(a) : "l"(p));
    return a;
}
__device__ __forceinline__ void ldsm_x4(uint32_t* r, uint32_t addr) {
    asm volatile("ldmatrix.sync.aligned.m8n8.x4.shared.b16 {%0,%1,%2,%3}, [%4];"
                 : "=r"(r[0]), "=r"(r[1]), "=r"(r[2]), "=r"(r[3]) : "r"(addr));
}
__device__ __forceinline__ void ldsm_x2(uint32_t* r, uint32_t addr) {
    asm volatile("ldmatrix.sync.aligned.m8n8.x2.shared.b16 {%0,%1}, [%2];"
                 : "=r"(r[0]), "=r"(r[1]) : "r"(addr));
}
__device__ __forceinline__ void mma_bf16(float* d, const uint32_t* a, const uint32_t* b) {
    asm volatile("mma.sync.aligned.m16n8k16.row.col.f32.bf16.bf16.f32 "
                 "{%0,%1,%2,%3}, {%4,%5,%6,%7}, {%8,%9}, {%0,%1,%2,%3};"
                 : "+f"(d[0]), "+f"(d[1]), "+f"(d[2]), "+f"(d[3])
                 : "r"(a[0]), "r"(a[1]), "r"(a[2]), "r"(a[3]), "r"(b[0]), "r"(b[1]));
}
__device__ __forceinline__ float sigf(float z) {
    return __fdividef(1.0f, 1.0f + __expf(-z));
}

// ============ Pass 1: transpose + hi/lo split ============
#define TP_T 4
__global__ void __launch_bounds__(256) transpose_x(const float* __restrict__ x) {
    __shared__ float sm[TP_T * 16 * 129];
    const int bx = blockIdx.x;
    const int t0 = (bx >> 3) * TP_T;
    const int b  = bx & 7;
    #pragma unroll 4
    for (int i = 0; i < 32; i++) {
        int idx  = i * 256 + threadIdx.x;
        int tloc = idx >> 11;
        int rem  = idx & 2047;                  // k*16 + nb
        float v = x[((size_t)(t0 + tloc) * BATCH + b) * 2048 + rem];
        sm[(tloc * 16 + (rem & 15)) * 129 + (rem >> 4)] = v;
    }
    __syncthreads();
    #pragma unroll 4
    for (int i = 0; i < 32; i++) {
        int idx = i * 256 + threadIdx.x;
        int k = idx & 127;
        int chunk = idx >> 7;                   // nb*4 + tloc
        int nb = chunk >> 2, tloc = chunk & 3;
        float v = sm[(tloc * 16 + nb) * 129 + k];
        __nv_bfloat16 hi = __float2bfloat16(v);
        __nv_bfloat16 lo = __float2bfloat16(v - __bfloat162float(hi));
        size_t o = ((size_t)(b * NBI + nb) * L_SEQ + t0 + tloc) * DIM + k;
        g_xhi[o] = hi;
        g_xlo[o] = lo;
    }
}

// ============ Pass 3: untranspose h ============
__global__ void __launch_bounds__(256) untranspose_h(float* __restrict__ out) {
    __shared__ float sm[TP_T * 16 * 129];
    const int bx = blockIdx.x;
    const int t0 = (bx >> 3) * TP_T;
    const int b  = bx & 7;
    #pragma unroll 4
    for (int i = 0; i < 32; i++) {
        int idx = i * 256 + threadIdx.x;
        int k = idx & 127;
        int chunk = idx >> 7;
        int nb = chunk >> 2, tloc = chunk & 3;
        sm[(tloc * 16 + nb) * 129 + k] =
            g_hT[((size_t)(b * NBI + nb) * L_SEQ + t0 + tloc) * DIM + k];
    }
    __syncthreads();
    #pragma unroll 4
    for (int i = 0; i < 32; i++) {
        int idx  = i * 256 + threadIdx.x;
        int tloc = idx >> 11;
        int rem  = idx & 2047;
        out[((size_t)(t0 + tloc) * BATCH + b) * 2048 + rem] =
            sm[(tloc * 16 + (rem & 15)) * 129 + (rem >> 4)];
    }
}

// ============ Pass 2: main (384 threads) ============
__global__ void __launch_bounds__(384, 1) sru_main(
    const float* __restrict__ W, const float* __restrict__ bias)
{
    extern __shared__ char sm[];
    const uint32_t sb = smem_u32(sm);
    const int tid  = threadIdx.x;
    const int lane = tid & 31;
    const int wid  = tid >> 5;
    const int bx = blockIdx.x, nb = bx & 15;
    const bool is_scan = (tid < 128);

    // ---- one-time: W^T hi/lo into swizzled SMEM (all 384 threads)
    {
        const float* Wp = W + (size_t)nb * (DIM * 3 * DIM);
        #pragma unroll 4
        for (int it = 0; it < 128; it++) {
            int idx = it * 384 + tid;            // = k*384 + h
            int k = idx / 384, h = idx - k * 384;
            float v = Wp[idx];
            __nv_bfloat16 hi = __float2bfloat16(v);
            __nv_bfloat16 lo = __float2bfloat16(v - __bfloat162float(hi));
            uint32_t byt = (uint32_t)h * 256 + (((k >> 3) ^ (h & 15)) << 4) + ((k & 7) * 2);
            *(__nv_bfloat16*)(sm + OFF_WHI + byt) = hi;
            *(__nv_bfloat16*)(sm + OFF_WLO + byt) = lo;
        }
    }
    // ---- scan-thread init + stage XB(0)
    const int j = tid;                           // channel (scan threads)
    float bfv = 0.0f, brv = 0.0f;
    if (is_scan) {
        bfv = bias[nb * 256 + j];
        brv = bias[nb * 256 + 128 + j];
        int t = tid >> 3, cc = (tid & 7) * 2;
        size_t o = ((size_t)bx * L_SEQ + t) * DIM + (tid & 7) * 16;
        const uint4* ph = (const uint4*)(g_xhi + o);
        const uint4* pl = (const uint4*)(g_xlo + o);
        uint4 H0 = ph[0], H1 = ph[1], L0 = pl[0], L1 = pl[1];
        uint32_t base = OFF_XB + (uint32_t)t * 256;
        *(uint4*)(sm + base + ((cc ^ t) << 4))       = H0;
        *(uint4*)(sm + base + (((cc + 1) ^ t) << 4)) = H1;
        *(uint4*)(sm + base + 4096 + ((cc ^ t) << 4))       = L0;
        *(uint4*)(sm + base + 4096 + (((cc + 1) ^ t) << 4)) = L1;
    }
    float c = 0.0f;
    float xt[NT], xv[NT];
    __half fh[NT], rh[NT];

    // GEMM lane/warp constants (warps 4-11 -> wg 0..7, mtiles 3*wg..3*wg+2)
    const int wg        = wid - 4;
    const int a_tile    = lane >> 3;
    const int a_row_add = (lane & 7) + ((a_tile & 1) << 3);
    const int a_chalf   = a_tile >> 1;
    const int b_row     = lane & 7;
    const int b_chalf   = (lane >> 3) & 1;
    const int g  = lane >> 2;
    const int tg = lane & 3;
    __syncthreads();

    for (int i = 0; i < NTILES; i++) {
        const int buf = i & 1;
        uint4 H0, H1, L0, L1;                    // scan-thread prefetch regs

        if (!is_scan) {
            // ---------- GEMM(i) (warps 4-11; identical to R7 inner loop)
            float D[3][2][4];
            #pragma unroll
            for (int mi = 0; mi < 3; mi++)
                #pragma unroll
                for (int nt = 0; nt < 2; nt++)
                    #pragma unroll
                    for (int e = 0; e < 4; e++) D[mi][nt][e] = 0.0f;

            const uint32_t xb = sb + OFF_XB + (uint32_t)buf * 8192;
            #pragma unroll
            for (int ks = 0; ks < 8; ks++) {
                uint32_t Bhi[2][2], Blo[2][2];
                #pragma unroll
                for (int nt = 0; nt < 2; nt++) {
                    int trow = nt * 8 + b_row;
                    uint32_t ba = xb + trow * 256 + (((2 * ks + b_chalf) ^ trow) << 4);
                    ldsm_x2(Bhi[nt], ba);
                    ldsm_x2(Blo[nt], ba + 4096);
                }
                #pragma unroll
                for (int mi = 0; mi < 3; mi++) {
                    int mt = wg * 3 + mi;
                    int row = mt * 16 + a_row_add;
                    uint32_t aa = sb + OFF_WHI + row * 256 +
                                  (((2 * ks + a_chalf) ^ (row & 15)) << 4);
                    uint32_t Ahi[4], Alo[4];
                    ldsm_x4(Ahi, aa);
                    ldsm_x4(Alo, aa + (OFF_WLO - OFF_WHI));
                    #pragma unroll
                    for (int nt = 0; nt < 2; nt++) {
                        mma_bf16(D[mi][nt], Ahi, Bhi[nt]);
                        mma_bf16(D[mi][nt], Alo, Bhi[nt]);
                        mma_bf16(D[mi][nt], Ahi, Blo[nt]);
                    }
                }
            }
            // -- store U(i)
            #pragma unroll
            for (int mi = 0; mi < 3; mi++) {
                int mt = wg * 3 + mi;
                int gate = mt >> 3;
                int h0 = (mt & 7) * 16 + g;
                #pragma unroll
                for (int nt = 0; nt < 2; nt++) {
                    int t0 = nt * 8 + tg * 2;
                    if (gate == 0) {
                        float* u = (float*)(sm + OFF_UX);
                        u[(t0)     * DIM + h0]     = D[mi][nt][0];
                        u[(t0 + 1) * DIM + h0]     = D[mi][nt][1];
                        u[(t0)     * DIM + h0 + 8] = D[mi][nt][2];
                        u[(t0 + 1) * DIM + h0 + 8] = D[mi][nt][3];
                    } else {
                        __half* u = (__half*)(sm + (gate == 1 ? OFF_UF : OFF_UR));
                        u[(t0)     * DIM + h0]     = __float2half_rn(D[mi][nt][0]);
                        u[(t0 + 1) * DIM + h0]     = __float2half_rn(D[mi][nt][1]);
                        u[(t0)     * DIM + h0 + 8] = __float2half_rn(D[mi][nt][2]);
                        u[(t0 + 1) * DIM + h0 + 8] = __float2half_rn(D[mi][nt][3]);
                    }
                }
            }
        } else {
            // ---------- scan(i-1) + LDG prefetch x(i+1) (warps 0-3), overlaps GEMM(i)
            if (i + 1 < NTILES) {
                int t = tid >> 3;
                size_t o = ((size_t)bx * L_SEQ + (size_t)(i + 1) * NT + t) * DIM + (tid & 7) * 16;
                const uint4* ph = (const uint4*)(g_xhi + o);
                const uint4* pl = (const uint4*)(g_xlo + o);
                H0 = ph[0]; H1 = ph[1]; L0 = pl[0]; L1 = pl[1];
            }
            if (i > 0) {
                float* hp = g_hT + ((size_t)bx * L_SEQ + (size_t)(i - 1) * NT) * DIM + j;
                #pragma unroll
                for (int t = 0; t < NT; t++) {
                    float fv = sigf(__half2float(fh[t]) + bfv);
                    float rv = sigf(__half2float(rh[t]) + brv);
                    c = fmaf(fv, c - xt[t], xt[t]);
                    hp[t * DIM] = fmaf(rv, c - xv[t], xv[t]);
                }
            }
        }
        __syncthreads();                         // U(i) visible; scan(i-1) done

        if (is_scan) {
            // -- stage XB(i+1) into the write-side buffer
            if (i + 1 < NTILES) {
                int t = tid >> 3, cc = (tid & 7) * 2;
                uint32_t base = OFF_XB + (uint32_t)((i + 1) & 1) * 8192 + (uint32_t)t * 256;
                *(uint4*)(sm + base + ((cc ^ t) << 4))       = H0;
                *(uint4*)(sm + base + (((cc + 1) ^ t) << 4)) = H1;
                *(uint4*)(sm + base + 4096 + ((cc ^ t) << 4))       = L0;
                *(uint4*)(sm + base + 4096 + (((cc + 1) ^ t) << 4)) = L1;
            }
            // -- drain U(i) and xv(i) into registers
            const float*  ux = (const float*)(sm + OFF_UX);
            const __half* uf = (const __half*)(sm + OFF_UF);
            const __half* ur = (const __half*)(sm + OFF_UR);
            const uint32_t xbb = OFF_XB + (uint32_t)buf * 8192;
            #pragma unroll
            for (int t = 0; t < NT; t++) {
                xt[t] = ux[t * DIM + j];
                fh[t] = uf[t * DIM + j];
                rh[t] = ur[t * DIM + j];
                uint32_t xa = xbb + t * 256 + (((j >> 3) ^ t) << 4) + ((j & 7) * 2);
                xv[t] = __bfloat162float(*(__nv_bfloat16*)(sm + xa)) +
                        __bfloat162float(*(__nv_bfloat16*)(sm + xa + 4096));
            }
        }
        __syncthreads();                         // U free; XB(buf) free
    }

    // -- final scan(NTILES-1)
    if (is_scan) {
        float* hp = g_hT + ((size_t)bx * L_SEQ + (size_t)(NTILES - 1) * NT) * DIM + j;
        #pragma unroll
        for (int t = 0; t < NT; t++) {
            float fv = sigf(__half2float(fh[t]) + bfv);
            float rv = sigf(__half2float(rh[t]) + brv);
            c = fmaf(fv, c - xt[t], xt[t]);
            hp[t * DIM] = fmaf(rv, c - xv[t], xv[t]);
        }
    }
}

extern "C" void kernel_launch(void* const* d_in, const int* in_sizes, int n_in,
                              void* d_out, int out_size) {
    const float* x  = (const float*)d_in[0];
    const float* W  = (const float*)d_in[1];
    const float* bi = (const float*)d_in[2];
    float* out = (float*)d_out;

    transpose_x<<<(L_SEQ / TP_T) * BATCH, 256>>>(x);
    cudaFuncSetAttribute(sru_main, cudaFuncAttributeMaxDynamicSharedMemorySize, SMEM_MAIN);
    sru_main<<<BATCH * NBI, 384, SMEM_MAIN>>>(W, bi);
    untranspose_h<<<(L_SEQ / TP_T) * BATCH, 256>>>(out);
}